// round 1
// baseline (speedup 1.0000x reference)
#include <cuda_runtime.h>
#include <math.h>

#define NA 8192
#define SD 64
#define HD 128
#define CD 32
#define AD 8

// -------- device scratch (no allocations allowed) --------
__device__ float g_P[NA * HD];      // states @ W1[:64]  (pre-bias)
__device__ float g_W2c[HD * CD];    // W2 @ Wc
__device__ float g_bc2[CD];         // b2 @ Wc + bc
__device__ float g_msum[CD];        // sum of normalized msgs
__device__ float g_hsum[HD];        // column sum of relu(P + bias_eff)
__device__ float g_gvec[HD];        // broadcast GNN output row

// ============ K0: fold W2c, bc2; zero accumulators. grid 32 x 128 ============
__global__ void k0(const float* __restrict__ W2, const float* __restrict__ Wc,
                   const float* __restrict__ b2, const float* __restrict__ bc) {
    int c = blockIdx.x;   // 0..31
    int t = threadIdx.x;  // 0..127
    float acc = 0.f;
#pragma unroll 8
    for (int k = 0; k < HD; k++) acc += W2[t * HD + k] * Wc[k * CD + c];
    g_W2c[t * CD + c] = acc;
    if (t == 0) {
        float a = bc[c];
        for (int k = 0; k < HD; k++) a += b2[k] * Wc[k * CD + c];
        g_bc2[c] = a;
    }
    if (c == 0) {
        if (t < CD) g_msum[t] = 0.f;
        g_hsum[t] = 0.f;
    }
}

// ============ K1: P = states@W1a ; msgs = l2norm(relu(P+b1)@W2c + bc2);
//              accumulate msg column sums. grid 512 x 128, 16 rows/block ======
#define K1_ROWS 16
__global__ void __launch_bounds__(128) k1(const float* __restrict__ states,
                                          const float* __restrict__ W1,
                                          const float* __restrict__ b1) {
    __shared__ float s_s[K1_ROWS * SD];       // 4 KB
    __shared__ float s_w2c[HD * CD];          // 16 KB
    __shared__ float s_h[K1_ROWS * HD];       // 8 KB
    __shared__ float s_msg[K1_ROWS][CD + 1];
    __shared__ float s_bc2[CD];
    __shared__ float s_rn[K1_ROWS];

    int t = threadIdx.x;
    int r0 = blockIdx.x * K1_ROWS;

    for (int i = t; i < K1_ROWS * SD; i += 128) s_s[i] = states[r0 * SD + i];
    for (int i = t; i < HD * CD; i += 128) s_w2c[i] = g_W2c[i];
    if (t < CD) s_bc2[t] = g_bc2[t];
    __syncthreads();

    float bb = b1[t];
    float acc[K1_ROWS];
#pragma unroll
    for (int r = 0; r < K1_ROWS; r++) acc[r] = 0.f;

#pragma unroll 4
    for (int k = 0; k < SD; k += 4) {
        float w0 = W1[(k + 0) * HD + t];
        float w1 = W1[(k + 1) * HD + t];
        float w2 = W1[(k + 2) * HD + t];
        float w3 = W1[(k + 3) * HD + t];
#pragma unroll
        for (int r = 0; r < K1_ROWS; r++) {
            float4 sv = *(const float4*)&s_s[r * SD + k];
            acc[r] += sv.x * w0;
            acc[r] += sv.y * w1;
            acc[r] += sv.z * w2;
            acc[r] += sv.w * w3;
        }
    }
#pragma unroll
    for (int r = 0; r < K1_ROWS; r++) {
        g_P[(r0 + r) * HD + t] = acc[r];
        s_h[r * HD + t] = fmaxf(acc[r] + bb, 0.f);
    }
    __syncthreads();

    // msgs: thread t -> col c = t&31, rows rg*4 .. rg*4+3 (rg = t>>5)
    int c = t & 31;
    int rg = t >> 5;
    float m0 = s_bc2[c], m1 = m0, m2 = m0, m3 = m0;
#pragma unroll 8
    for (int k = 0; k < HD; k += 4) {
        float w0 = s_w2c[(k + 0) * CD + c];
        float w1 = s_w2c[(k + 1) * CD + c];
        float w2 = s_w2c[(k + 2) * CD + c];
        float w3 = s_w2c[(k + 3) * CD + c];
        float4 ha = *(const float4*)&s_h[(rg * 4 + 0) * HD + k];
        float4 hb = *(const float4*)&s_h[(rg * 4 + 1) * HD + k];
        float4 hc = *(const float4*)&s_h[(rg * 4 + 2) * HD + k];
        float4 hd = *(const float4*)&s_h[(rg * 4 + 3) * HD + k];
        m0 += ha.x * w0 + ha.y * w1 + ha.z * w2 + ha.w * w3;
        m1 += hb.x * w0 + hb.y * w1 + hb.z * w2 + hb.w * w3;
        m2 += hc.x * w0 + hc.y * w1 + hc.z * w2 + hc.w * w3;
        m3 += hd.x * w0 + hd.y * w1 + hd.z * w2 + hd.w * w3;
    }
    s_msg[rg * 4 + 0][c] = m0;
    s_msg[rg * 4 + 1][c] = m1;
    s_msg[rg * 4 + 2][c] = m2;
    s_msg[rg * 4 + 3][c] = m3;
    __syncthreads();

    if (t < K1_ROWS) {
        float ss = 0.f;
#pragma unroll
        for (int j = 0; j < CD; j++) { float v = s_msg[t][j]; ss += v * v; }
        s_rn[t] = 1.f / fmaxf(sqrtf(ss), 1e-12f);
    }
    __syncthreads();
    if (t < CD) {
        float p = 0.f;
#pragma unroll
        for (int r = 0; r < K1_ROWS; r++) p += s_msg[r][t] * s_rn[r];
        atomicAdd(&g_msum[t], p);
    }
}

// ============ K3: hsum[c] = sum_r relu(P[r][c] + bias_eff[c]).
//              grid 128 x 128, 64 rows/block ============
#define K3_ROWS 64
__global__ void __launch_bounds__(128) k3(const float* __restrict__ W1,
                                          const float* __restrict__ b1) {
    __shared__ float s_be[HD];
    __shared__ float s_col[HD];
    int t = threadIdx.x;
    float be = b1[t];
#pragma unroll
    for (int k = 0; k < CD; k++)
        be += (g_msum[k] * (1.0f / NA)) * W1[(SD + k) * HD + t];
    s_be[t] = be;
    s_col[t] = 0.f;
    __syncthreads();

    int r0 = blockIdx.x * K3_ROWS;
    int c4 = (t & 31) * 4;
    int rr = t >> 5;
    float4 be4 = *(const float4*)&s_be[c4];
    float s0 = 0.f, s1 = 0.f, s2 = 0.f, s3 = 0.f;
    for (int r = rr; r < K3_ROWS; r += 4) {
        float4 p = *(const float4*)&g_P[(size_t)(r0 + r) * HD + c4];
        s0 += fmaxf(p.x + be4.x, 0.f);
        s1 += fmaxf(p.y + be4.y, 0.f);
        s2 += fmaxf(p.z + be4.z, 0.f);
        s3 += fmaxf(p.w + be4.w, 0.f);
    }
    atomicAdd(&s_col[c4 + 0], s0);
    atomicAdd(&s_col[c4 + 1], s1);
    atomicAdd(&s_col[c4 + 2], s2);
    atomicAdd(&s_col[c4 + 3], s3);
    __syncthreads();
    atomicAdd(&g_hsum[t], s_col[t]);
}

// ============ K4: g = relu((mean_h @ W2 + b2) @ Wg + bg). 1 x 128 ============
__global__ void k4(const float* __restrict__ W2, const float* __restrict__ b2,
                   const float* __restrict__ Wg, const float* __restrict__ bg) {
    __shared__ float s_mh[HD];
    __shared__ float s_h2[HD];
    int t = threadIdx.x;
    s_mh[t] = g_hsum[t] * (1.0f / NA);
    __syncthreads();
    float a = b2[t];
#pragma unroll 8
    for (int k = 0; k < HD; k++) a += s_mh[k] * W2[k * HD + t];
    s_h2[t] = a;
    __syncthreads();
    float g = bg[t];
#pragma unroll 8
    for (int k = 0; k < HD; k++) g += s_h2[k] * Wg[k * HD + t];
    g_gvec[t] = fmaxf(g, 0.f);
}

// ============ K5: H = l2norm(g + 0.01*noise); heads. grid 1024 x 256 ============
#define K5_ROWS 8
__global__ void __launch_bounds__(256) k5(const float* __restrict__ noise,
                                          const float* __restrict__ Wp,
                                          const float* __restrict__ bp,
                                          const float* __restrict__ Wv,
                                          const float* __restrict__ bv,
                                          const float* __restrict__ Wr,
                                          const float* __restrict__ br,
                                          float* __restrict__ outH,
                                          float* __restrict__ outA,
                                          float* __restrict__ outV,
                                          float* __restrict__ outR) {
    __shared__ float s_g[HD];
    __shared__ float s_hw[HD * 12];          // combined head weights [k][12]
    __shared__ float s_hrow[K5_ROWS][HD];
    __shared__ float s_head[K5_ROWS][12];

    int t = threadIdx.x;
    if (t < HD) s_g[t] = g_gvec[t];
    for (int i = t; i < HD * 12; i += 256) {
        int k = i / 12, j = i % 12;
        float v;
        if (j < 8)      v = Wp[k * AD + j];
        else if (j == 8) v = Wv[k];
        else            v = Wr[k * 3 + (j - 9)];
        s_hw[i] = v;
    }
    __syncthreads();

    int w = t >> 5;
    int lane = t & 31;
    int row = blockIdx.x * K5_ROWS + w;
    const float* nr = noise + (size_t)row * HD;

    float v0 = s_g[lane +  0] + 0.01f * nr[lane +  0];
    float v1 = s_g[lane + 32] + 0.01f * nr[lane + 32];
    float v2 = s_g[lane + 64] + 0.01f * nr[lane + 64];
    float v3 = s_g[lane + 96] + 0.01f * nr[lane + 96];
    float ss = v0 * v0 + v1 * v1 + v2 * v2 + v3 * v3;
#pragma unroll
    for (int o = 16; o; o >>= 1) ss += __shfl_xor_sync(0xffffffffu, ss, o);
    float rn = 1.f / fmaxf(sqrtf(ss), 1e-12f);
    float h0 = v0 * rn, h1 = v1 * rn, h2 = v2 * rn, h3 = v3 * rn;

    float* oh = outH + (size_t)row * HD;
    oh[lane +  0] = h0;
    oh[lane + 32] = h1;
    oh[lane + 64] = h2;
    oh[lane + 96] = h3;
    s_hrow[w][lane +  0] = h0;
    s_hrow[w][lane + 32] = h1;
    s_hrow[w][lane + 64] = h2;
    s_hrow[w][lane + 96] = h3;
    __syncwarp();

    if (lane < 12) {
        float d = 0.f;
#pragma unroll 8
        for (int k = 0; k < HD; k++) d += s_hrow[w][k] * s_hw[k * 12 + lane];
        s_head[w][lane] = d;
    }
    __syncwarp();

    if (lane < 8) {
        outA[(size_t)row * AD + lane] = tanhf(s_head[w][lane] + bp[lane]);
    } else if (lane == 8) {
        outV[row] = s_head[w][8] + bv[0];
    } else if (lane == 9) {
        float z0 = s_head[w][9]  + br[0];
        float z1 = s_head[w][10] + br[1];
        float z2 = s_head[w][11] + br[2];
        float m = fmaxf(z0, fmaxf(z1, z2));
        float e0 = expf(z0 - m), e1 = expf(z1 - m), e2 = expf(z2 - m);
        float inv = 1.f / (e0 + e1 + e2);
        outR[(size_t)row * 3 + 0] = e0 * inv;
        outR[(size_t)row * 3 + 1] = e1 * inv;
        outR[(size_t)row * 3 + 2] = e2 * inv;
    }
}

extern "C" void kernel_launch(void* const* d_in, const int* in_sizes, int n_in,
                              void* d_out, int out_size) {
    const float* states = (const float*)d_in[0];
    const float* noise  = (const float*)d_in[1];
    const float* W1 = (const float*)d_in[2];
    const float* b1 = (const float*)d_in[3];
    const float* W2 = (const float*)d_in[4];
    const float* b2 = (const float*)d_in[5];
    const float* Wc = (const float*)d_in[6];
    const float* bc = (const float*)d_in[7];
    const float* Wg = (const float*)d_in[8];
    const float* bg = (const float*)d_in[9];
    const float* Wp = (const float*)d_in[10];
    const float* bp = (const float*)d_in[11];
    const float* Wv = (const float*)d_in[12];
    const float* bv = (const float*)d_in[13];
    const float* Wr = (const float*)d_in[14];
    const float* br = (const float*)d_in[15];

    float* outH = (float*)d_out;                       // [N, HD]
    float* outA = outH + (size_t)NA * HD;              // [N, AD]
    float* outV = outA + (size_t)NA * AD;              // [N, 1]
    float* outR = outV + (size_t)NA;                   // [N, 3]

    k0<<<CD, 128>>>(W2, Wc, b2, bc);
    k1<<<NA / K1_ROWS, 128>>>(states, W1, b1);
    k3<<<NA / K3_ROWS, 128>>>(W1, b1);
    k4<<<1, 128>>>(W2, b2, Wg, bg);
    k5<<<NA / K5_ROWS, 256>>>(noise, Wp, bp, Wv, bv, Wr, br,
                              outH, outA, outV, outR);
}

// round 2
// speedup vs baseline: 1.0383x; 1.0383x over previous
#include <cuda_runtime.h>
#include <math.h>

#define NA 8192
#define SD 64
#define HD 128
#define CD 32
#define AD 8

// -------- device scratch (no allocations allowed) --------
__device__ float g_P[NA * HD];      // states @ W1[:64]  (pre-bias)
__device__ float g_W2c[HD * CD];    // W2 @ Wc
__device__ float g_bc2[CD];         // b2 @ Wc + bc
__device__ float g_msum[CD];        // sum of normalized msgs
__device__ float g_hsum[HD];        // column sum of relu(P + bias_eff)
__device__ float g_gvec[HD];        // broadcast GNN output row

// ============ K0: fold W2c, bc2; zero accumulators. grid 32 x 128 ============
__global__ void k0(const float* __restrict__ W2, const float* __restrict__ Wc,
                   const float* __restrict__ b2, const float* __restrict__ bc) {
    int c = blockIdx.x;   // 0..31
    int t = threadIdx.x;  // 0..127
    float acc = 0.f;
#pragma unroll 8
    for (int k = 0; k < HD; k++) acc += W2[t * HD + k] * Wc[k * CD + c];
    g_W2c[t * CD + c] = acc;
    if (t == 0) {
        float a = bc[c];
        for (int k = 0; k < HD; k++) a += b2[k] * Wc[k * CD + c];
        g_bc2[c] = a;
    }
    if (c == 0) {
        if (t < CD) g_msum[t] = 0.f;
        g_hsum[t] = 0.f;
    }
}

// ============ K1: P = states@W1a ; msgs = l2norm(relu(P+b1)@W2c + bc2);
//              accumulate msg column sums. grid 256 x 128, 32 rows/block ======
#define K1_ROWS 32
__global__ void __launch_bounds__(128) k1(const float* __restrict__ states,
                                          const float* __restrict__ W1,
                                          const float* __restrict__ b1) {
    __shared__ __align__(16) float s_s[K1_ROWS * SD];   // 8 KB
    __shared__ __align__(16) float s_w2c[HD * CD];      // 16 KB
    __shared__ __align__(16) float s_h[K1_ROWS * HD];   // 16 KB
    __shared__ float s_msg[K1_ROWS][CD + 1];            // ~4.2 KB
    __shared__ float s_bc2[CD];
    __shared__ float s_rn[K1_ROWS];

    int t = threadIdx.x;
    int r0 = blockIdx.x * K1_ROWS;

    for (int i = t; i < K1_ROWS * SD; i += 128) s_s[i] = states[r0 * SD + i];
    for (int i = t; i < HD * CD; i += 128) s_w2c[i] = g_W2c[i];
    if (t < CD) s_bc2[t] = g_bc2[t];
    __syncthreads();

    float bb = b1[t];
    float acc[K1_ROWS];
#pragma unroll
    for (int r = 0; r < K1_ROWS; r++) acc[r] = 0.f;

#pragma unroll 4
    for (int k = 0; k < SD; k += 4) {
        float w0 = W1[(k + 0) * HD + t];
        float w1 = W1[(k + 1) * HD + t];
        float w2 = W1[(k + 2) * HD + t];
        float w3 = W1[(k + 3) * HD + t];
#pragma unroll
        for (int r = 0; r < K1_ROWS; r++) {
            float4 sv = *(const float4*)&s_s[r * SD + k];
            acc[r] += sv.x * w0;
            acc[r] += sv.y * w1;
            acc[r] += sv.z * w2;
            acc[r] += sv.w * w3;
        }
    }
#pragma unroll
    for (int r = 0; r < K1_ROWS; r++) {
        g_P[(size_t)(r0 + r) * HD + t] = acc[r];
        s_h[r * HD + t] = fmaxf(acc[r] + bb, 0.f);
    }
    __syncthreads();

    // msgs: thread t -> col c = t&31, rows rg*8 .. rg*8+7 (rg = t>>5)
    int c = t & 31;
    int rg = t >> 5;
    float m[8];
#pragma unroll
    for (int r = 0; r < 8; r++) m[r] = s_bc2[c];
#pragma unroll 8
    for (int k = 0; k < HD; k += 4) {
        float w0 = s_w2c[(k + 0) * CD + c];
        float w1 = s_w2c[(k + 1) * CD + c];
        float w2 = s_w2c[(k + 2) * CD + c];
        float w3 = s_w2c[(k + 3) * CD + c];
#pragma unroll
        for (int r = 0; r < 8; r++) {
            float4 hv = *(const float4*)&s_h[(rg * 8 + r) * HD + k];
            m[r] += hv.x * w0 + hv.y * w1 + hv.z * w2 + hv.w * w3;
        }
    }
#pragma unroll
    for (int r = 0; r < 8; r++) s_msg[rg * 8 + r][c] = m[r];
    __syncthreads();

    if (t < K1_ROWS) {
        float ss = 0.f;
#pragma unroll
        for (int j = 0; j < CD; j++) { float v = s_msg[t][j]; ss += v * v; }
        s_rn[t] = 1.f / fmaxf(sqrtf(ss), 1e-12f);
    }
    __syncthreads();
    if (t < CD) {
        float p = 0.f;
#pragma unroll
        for (int r = 0; r < K1_ROWS; r++) p += s_msg[r][t] * s_rn[r];
        atomicAdd(&g_msum[t], p);
    }
}

// ============ K3: hsum[c] = sum_r relu(P[r][c] + bias_eff[c]).
//              grid 128 x 128, 64 rows/block ============
#define K3_ROWS 64
__global__ void __launch_bounds__(128) k3(const float* __restrict__ W1,
                                          const float* __restrict__ b1) {
    __shared__ __align__(16) float s_be[HD];
    __shared__ float s_col[HD];
    int t = threadIdx.x;
    float be = b1[t];
#pragma unroll
    for (int k = 0; k < CD; k++)
        be += (g_msum[k] * (1.0f / NA)) * W1[(SD + k) * HD + t];
    s_be[t] = be;
    s_col[t] = 0.f;
    __syncthreads();

    int r0 = blockIdx.x * K3_ROWS;
    int c4 = (t & 31) * 4;
    int rr = t >> 5;
    float4 be4 = *(const float4*)&s_be[c4];
    float s0 = 0.f, s1 = 0.f, s2 = 0.f, s3 = 0.f;
    for (int r = rr; r < K3_ROWS; r += 4) {
        float4 p = *(const float4*)&g_P[(size_t)(r0 + r) * HD + c4];
        s0 += fmaxf(p.x + be4.x, 0.f);
        s1 += fmaxf(p.y + be4.y, 0.f);
        s2 += fmaxf(p.z + be4.z, 0.f);
        s3 += fmaxf(p.w + be4.w, 0.f);
    }
    atomicAdd(&s_col[c4 + 0], s0);
    atomicAdd(&s_col[c4 + 1], s1);
    atomicAdd(&s_col[c4 + 2], s2);
    atomicAdd(&s_col[c4 + 3], s3);
    __syncthreads();
    atomicAdd(&g_hsum[t], s_col[t]);
}

// ============ K4: g = relu((mean_h @ W2 + b2) @ Wg + bg). 1 x 1024 ============
// 8-way split-K per output column; ALL weight loads front-batched into regs.
__global__ void __launch_bounds__(1024) k4(const float* __restrict__ W2,
                                           const float* __restrict__ b2,
                                           const float* __restrict__ Wg,
                                           const float* __restrict__ bg) {
    __shared__ float s_mh[HD];
    __shared__ float s_part[8][HD];
    __shared__ float s_h2[HD];
    int t = threadIdx.x;
    int out = t & 127;   // output column
    int part = t >> 7;   // 0..7, k-range [part*16, part*16+16)

    // front-batch all 32 weight loads (one DRAM round trip, MLP=32)
    float w2r[16], wgr[16];
#pragma unroll
    for (int i = 0; i < 16; i++) {
        int k = part * 16 + i;
        w2r[i] = W2[k * HD + out];
        wgr[i] = Wg[k * HD + out];
    }
    if (t < HD) s_mh[t] = g_hsum[t] * (1.0f / NA);
    __syncthreads();

    float a = 0.f;
#pragma unroll
    for (int i = 0; i < 16; i++) a += s_mh[part * 16 + i] * w2r[i];
    s_part[part][out] = a;
    __syncthreads();

    if (t < HD) {
        float v = b2[t];
#pragma unroll
        for (int p = 0; p < 8; p++) v += s_part[p][t];
        s_h2[t] = v;
    }
    __syncthreads();

    float g = 0.f;
#pragma unroll
    for (int i = 0; i < 16; i++) g += s_h2[part * 16 + i] * wgr[i];
    s_part[part][out] = g;
    __syncthreads();

    if (t < HD) {
        float v = bg[t];
#pragma unroll
        for (int p = 0; p < 8; p++) v += s_part[p][t];
        g_gvec[t] = fmaxf(v, 0.f);
    }
}

// ============ K5: H = l2norm(g + 0.01*noise); heads. grid 1024 x 256 ============
#define K5_ROWS 8
__global__ void __launch_bounds__(256) k5(const float* __restrict__ noise,
                                          const float* __restrict__ Wp,
                                          const float* __restrict__ bp,
                                          const float* __restrict__ Wv,
                                          const float* __restrict__ bv,
                                          const float* __restrict__ Wr,
                                          const float* __restrict__ br,
                                          float* __restrict__ outH,
                                          float* __restrict__ outA,
                                          float* __restrict__ outV,
                                          float* __restrict__ outR) {
    __shared__ float s_g[HD];
    __shared__ __align__(16) float s_hw[HD * 12];  // combined head weights [k][12]

    int t = threadIdx.x;
    if (t < HD) s_g[t] = g_gvec[t];
    for (int i = t; i < HD * 12; i += 256) {
        int k = i / 12, j = i % 12;
        float v;
        if (j < 8)       v = Wp[k * AD + j];
        else if (j == 8) v = Wv[k];
        else             v = Wr[k * 3 + (j - 9)];
        s_hw[i] = v;
    }
    __syncthreads();

    int w = t >> 5;
    int lane = t & 31;
    int row = blockIdx.x * K5_ROWS + w;
    const float* nr = noise + (size_t)row * HD;

    float v0 = s_g[lane +  0] + 0.01f * nr[lane +  0];
    float v1 = s_g[lane + 32] + 0.01f * nr[lane + 32];
    float v2 = s_g[lane + 64] + 0.01f * nr[lane + 64];
    float v3 = s_g[lane + 96] + 0.01f * nr[lane + 96];
    float ss = v0 * v0 + v1 * v1 + v2 * v2 + v3 * v3;
#pragma unroll
    for (int o = 16; o; o >>= 1) ss += __shfl_xor_sync(0xffffffffu, ss, o);
    float rn = 1.f / fmaxf(sqrtf(ss), 1e-12f);
    float h[4] = {v0 * rn, v1 * rn, v2 * rn, v3 * rn};

    float* oh = outH + (size_t)row * HD;
    oh[lane +  0] = h[0];
    oh[lane + 32] = h[1];
    oh[lane + 64] = h[2];
    oh[lane + 96] = h[3];

    // heads: lane-parallel partial dot products over this lane's 4 k values
    float hd_[12];
#pragma unroll
    for (int j = 0; j < 12; j++) hd_[j] = 0.f;
#pragma unroll
    for (int m = 0; m < 4; m++) {
        int k = lane + 32 * m;
        const float4* wrow = (const float4*)&s_hw[k * 12];
        float4 wa = wrow[0], wb = wrow[1], wc = wrow[2];
        float hv = h[m];
        hd_[0] += hv * wa.x;  hd_[1] += hv * wa.y;  hd_[2]  += hv * wa.z;  hd_[3]  += hv * wa.w;
        hd_[4] += hv * wb.x;  hd_[5] += hv * wb.y;  hd_[6]  += hv * wb.z;  hd_[7]  += hv * wb.w;
        hd_[8] += hv * wc.x;  hd_[9] += hv * wc.y;  hd_[10] += hv * wc.z;  hd_[11] += hv * wc.w;
    }
#pragma unroll
    for (int j = 0; j < 12; j++) {
#pragma unroll
        for (int o = 16; o; o >>= 1) hd_[j] += __shfl_xor_sync(0xffffffffu, hd_[j], o);
    }

    if (lane < 8) {
        outA[(size_t)row * AD + lane] = tanhf(hd_[lane] + bp[lane]);
    } else if (lane == 8) {
        outV[row] = hd_[8] + bv[0];
    } else if (lane == 9) {
        float z0 = hd_[9]  + br[0];
        float z1 = hd_[10] + br[1];
        float z2 = hd_[11] + br[2];
        float mx = fmaxf(z0, fmaxf(z1, z2));
        float e0 = expf(z0 - mx), e1 = expf(z1 - mx), e2 = expf(z2 - mx);
        float inv = 1.f / (e0 + e1 + e2);
        outR[(size_t)row * 3 + 0] = e0 * inv;
        outR[(size_t)row * 3 + 1] = e1 * inv;
        outR[(size_t)row * 3 + 2] = e2 * inv;
    }
}

extern "C" void kernel_launch(void* const* d_in, const int* in_sizes, int n_in,
                              void* d_out, int out_size) {
    const float* states = (const float*)d_in[0];
    const float* noise  = (const float*)d_in[1];
    const float* W1 = (const float*)d_in[2];
    const float* b1 = (const float*)d_in[3];
    const float* W2 = (const float*)d_in[4];
    const float* b2 = (const float*)d_in[5];
    const float* Wc = (const float*)d_in[6];
    const float* bc = (const float*)d_in[7];
    const float* Wg = (const float*)d_in[8];
    const float* bg = (const float*)d_in[9];
    const float* Wp = (const float*)d_in[10];
    const float* bp = (const float*)d_in[11];
    const float* Wv = (const float*)d_in[12];
    const float* bv = (const float*)d_in[13];
    const float* Wr = (const float*)d_in[14];
    const float* br = (const float*)d_in[15];

    float* outH = (float*)d_out;                       // [N, HD]
    float* outA = outH + (size_t)NA * HD;              // [N, AD]
    float* outV = outA + (size_t)NA * AD;              // [N, 1]
    float* outR = outV + (size_t)NA;                   // [N, 3]

    k0<<<CD, 128>>>(W2, Wc, b2, bc);
    k1<<<NA / K1_ROWS, 128>>>(states, W1, b1);
    k3<<<NA / K3_ROWS, 128>>>(W1, b1);
    k4<<<1, 1024>>>(W2, b2, Wg, bg);
    k5<<<NA / K5_ROWS, 256>>>(noise, Wp, bp, Wv, bv, Wr, br,
                              outH, outA, outV, outR);
}

// round 3
// speedup vs baseline: 1.0769x; 1.0372x over previous
#include <cuda_runtime.h>
#include <math.h>

#define NA 8192
#define SD 64
#define HD 128
#define CD 32
#define AD 8
#define NB 128      // fused grid (<= 148 SMs -> all resident, grid barrier safe)
#define NT 256
#define ROWS 64     // rows per block
#define RPT 32      // rows per thread (two half-warpsets of 128 threads)

// -------- device scratch --------
__device__ float g_W2c[HD * CD];    // W2 @ Wc
__device__ float g_bc2[CD];         // b2 @ Wc + bc
__device__ float g_msum[CD];        // sum of normalized msgs
__device__ float g_hsum[HD];        // column sum of relu(P + bias_eff)
__device__ unsigned g_barA, g_barB; // grid barrier counters (reset by k0)

// ============ K0: fold W2c, bc2; zero accumulators + barriers. 32 x 128 ======
__global__ void k0(const float* __restrict__ W2, const float* __restrict__ Wc,
                   const float* __restrict__ b2, const float* __restrict__ bc) {
    int c = blockIdx.x;   // 0..31
    int t = threadIdx.x;  // 0..127
    float acc = 0.f;
#pragma unroll 8
    for (int k = 0; k < HD; k++) acc += W2[t * HD + k] * Wc[k * CD + c];
    g_W2c[t * CD + c] = acc;
    if (t == 0) {
        float a = bc[c];
        for (int k = 0; k < HD; k++) a += b2[k] * Wc[k * CD + c];
        g_bc2[c] = a;
    }
    if (c == 0) {
        if (t < CD) g_msum[t] = 0.f;
        g_hsum[t] = 0.f;
        if (t == 0) { g_barA = 0u; g_barB = 0u; }
    }
}

// ---- software grid barrier (all NB blocks resident) ----
__device__ __forceinline__ void grid_barrier(unsigned* ctr) {
    __syncthreads();
    if (threadIdx.x == 0) {
        __threadfence();
        atomicAdd(ctr, 1u);
        while (*(volatile unsigned*)ctr < (unsigned)NB) {}
    }
    __syncthreads();
}

// ============ FUSED: k1 + k3 + k4 + k5 ============
__global__ void __launch_bounds__(NT, 1) kfused(
    const float* __restrict__ states, const float* __restrict__ noise,
    const float* __restrict__ W1, const float* __restrict__ b1,
    const float* __restrict__ W2, const float* __restrict__ b2,
    const float* __restrict__ Wg, const float* __restrict__ bg,
    const float* __restrict__ Wp, const float* __restrict__ bp,
    const float* __restrict__ Wv, const float* __restrict__ bv,
    const float* __restrict__ Wr, const float* __restrict__ br,
    float* __restrict__ outH, float* __restrict__ outA,
    float* __restrict__ outV, float* __restrict__ outR) {

    extern __shared__ float sm[];
    float* s_s   = sm;                    // ROWS*SD   = 4096
    float* s_w2c = s_s   + ROWS * SD;     // HD*CD     = 4096
    float* s_h   = s_w2c + HD * CD;       // ROWS*HD   = 8192
    float* s_msg = s_h   + ROWS * HD;     // ROWS*33   = 2112
    float* s_rn  = s_msg + ROWS * 33;     // 64
    float* s_bc2 = s_rn  + ROWS;          // 32
    float* s_mh  = s_bc2 + CD;            // 128
    float* s_h2  = s_mh  + HD;            // 128
    float* s_g   = s_h2  + HD;            // 128
    float* s_prt = s_g   + HD;            // 256
    float* s_hw  = s_prt + 2 * HD;        // 1536

    int t = threadIdx.x;
    int r0 = blockIdx.x * ROWS;

    // ---- stage shared inputs ----
    for (int i = t; i < ROWS * SD; i += NT) s_s[i] = states[r0 * SD + i];
    for (int i = t; i < HD * CD; i += NT) s_w2c[i] = g_W2c[i];
    if (t < CD) s_bc2[t] = g_bc2[t];
    for (int i = t; i < HD * 12; i += NT) {
        int k = i / 12, j = i % 12;
        float v;
        if (j < 8)       v = Wp[k * AD + j];
        else if (j == 8) v = Wv[k];
        else             v = Wr[k * 3 + (j - 9)];
        s_hw[i] = v;
    }
    __syncthreads();

    // ---- phase 1: P = states @ W1[:SD] (held in registers) ----
    int c = t & 127;              // output column
    int rb = (t >> 7) * RPT;      // row base (0 or 32)
    float bb = b1[c];
    float acc[RPT];
#pragma unroll
    for (int r = 0; r < RPT; r++) acc[r] = 0.f;

    for (int k = 0; k < SD; k += 4) {
        float w0 = W1[(k + 0) * HD + c];
        float w1 = W1[(k + 1) * HD + c];
        float w2 = W1[(k + 2) * HD + c];
        float w3 = W1[(k + 3) * HD + c];
#pragma unroll
        for (int r = 0; r < RPT; r++) {
            float4 sv = *(const float4*)&s_s[(rb + r) * SD + k];
            acc[r] += sv.x * w0 + sv.y * w1 + sv.z * w2 + sv.w * w3;
        }
    }
#pragma unroll
    for (int r = 0; r < RPT; r++)
        s_h[(rb + r) * HD + c] = fmaxf(acc[r] + bb, 0.f);
    __syncthreads();

    // ---- phase 2: msgs = l2norm(relu(P+b1) @ W2c + bc2); accumulate msum ----
    {
        int mc = t & 31;          // msg column
        int rg = t >> 5;          // 0..7, 8 rows each
        float m[8];
#pragma unroll
        for (int r = 0; r < 8; r++) m[r] = s_bc2[mc];
        for (int k = 0; k < HD; k += 4) {
            float w0 = s_w2c[(k + 0) * CD + mc];
            float w1 = s_w2c[(k + 1) * CD + mc];
            float w2 = s_w2c[(k + 2) * CD + mc];
            float w3 = s_w2c[(k + 3) * CD + mc];
#pragma unroll
            for (int r = 0; r < 8; r++) {
                float4 hv = *(const float4*)&s_h[(rg * 8 + r) * HD + k];
                m[r] += hv.x * w0 + hv.y * w1 + hv.z * w2 + hv.w * w3;
            }
        }
#pragma unroll
        for (int r = 0; r < 8; r++) s_msg[(rg * 8 + r) * 33 + mc] = m[r];
    }
    __syncthreads();
    if (t < ROWS) {
        float ss = 0.f;
#pragma unroll
        for (int j = 0; j < CD; j++) { float v = s_msg[t * 33 + j]; ss += v * v; }
        s_rn[t] = 1.f / fmaxf(sqrtf(ss), 1e-12f);
    }
    __syncthreads();
    if (t < CD) {
        float p = 0.f;
#pragma unroll
        for (int r = 0; r < ROWS; r++) p += s_msg[r * 33 + t] * s_rn[r];
        atomicAdd(&g_msum[t], p);
    }

    grid_barrier(&g_barA);

    // ---- phase 3: hsum[c] += sum_r relu(acc[r] + bias_eff[c]) ----
    if (t < CD) s_bc2[t] = *(volatile float*)&g_msum[t];  // reuse s_bc2
    __syncthreads();
    {
        float be = bb;
#pragma unroll
        for (int j = 0; j < CD; j++)
            be += (s_bc2[j] * (1.0f / NA)) * W1[(SD + j) * HD + c];
        float hp = 0.f;
#pragma unroll
        for (int r = 0; r < RPT; r++) hp += fmaxf(acc[r] + be, 0.f);
        atomicAdd(&g_hsum[c], hp);
    }

    grid_barrier(&g_barB);

    // ---- phase 4: g = relu((mean_h @ W2 + b2) @ Wg + bg), redundant/block ----
    if (t < HD) s_mh[t] = *(volatile float*)&g_hsum[t] * (1.0f / NA);
    __syncthreads();
    {
        int part = t >> 7;  // split-K in 2 halves
        float a = 0.f;
#pragma unroll 8
        for (int i = 0; i < 64; i++) {
            int k = part * 64 + i;
            a += s_mh[k] * W2[k * HD + c];
        }
        s_prt[part * HD + c] = a;
        __syncthreads();
        if (t < HD) s_h2[t] = b2[t] + s_prt[t] + s_prt[HD + t];
        __syncthreads();
        float g2 = 0.f;
#pragma unroll 8
        for (int i = 0; i < 64; i++) {
            int k = part * 64 + i;
            g2 += s_h2[k] * Wg[k * HD + c];
        }
        s_prt[part * HD + c] = g2;
        __syncthreads();
        if (t < HD) s_g[t] = fmaxf(bg[t] + s_prt[t] + s_prt[HD + t], 0.f);
        __syncthreads();
    }

    // ---- phase 5: H = l2norm(g + 0.01*noise); heads. 8 rows per warp ----
    {
        int w = t >> 5, lane = t & 31;
        int rowb = r0 + w * 8;
        const float* nb = noise + (size_t)rowb * HD;
        float gp0 = s_g[lane +  0], gp1 = s_g[lane + 32];
        float gp2 = s_g[lane + 64], gp3 = s_g[lane + 96];
        float bpv = (lane < 8) ? bp[lane] : 0.f;
        float bvv = bv[0];
        float br0 = br[0], br1 = br[1], br2 = br[2];

        float na0 = nb[lane], na1 = nb[lane + 32];
        float na2 = nb[lane + 64], na3 = nb[lane + 96];

#pragma unroll
        for (int i = 0; i < 8; i++) {
            float c0 = na0, c1 = na1, c2 = na2, c3 = na3;
            if (i < 7) {
                const float* nn = nb + (i + 1) * HD;
                na0 = nn[lane]; na1 = nn[lane + 32];
                na2 = nn[lane + 64]; na3 = nn[lane + 96];
            }
            int row = rowb + i;
            float v0 = gp0 + 0.01f * c0;
            float v1 = gp1 + 0.01f * c1;
            float v2 = gp2 + 0.01f * c2;
            float v3 = gp3 + 0.01f * c3;
            float ss = v0 * v0 + v1 * v1 + v2 * v2 + v3 * v3;
#pragma unroll
            for (int o = 16; o; o >>= 1) ss += __shfl_xor_sync(0xffffffffu, ss, o);
            float rn = 1.f / fmaxf(sqrtf(ss), 1e-12f);
            float h[4] = {v0 * rn, v1 * rn, v2 * rn, v3 * rn};

            float* oh = outH + (size_t)row * HD;
            oh[lane +  0] = h[0];
            oh[lane + 32] = h[1];
            oh[lane + 64] = h[2];
            oh[lane + 96] = h[3];

            float hd_[12];
#pragma unroll
            for (int j = 0; j < 12; j++) hd_[j] = 0.f;
#pragma unroll
            for (int m = 0; m < 4; m++) {
                int k = lane + 32 * m;
                const float4* wrow = (const float4*)&s_hw[k * 12];
                float4 wa = wrow[0], wb2 = wrow[1], wc2 = wrow[2];
                float hv = h[m];
                hd_[0] += hv * wa.x;  hd_[1] += hv * wa.y;
                hd_[2] += hv * wa.z;  hd_[3] += hv * wa.w;
                hd_[4] += hv * wb2.x; hd_[5] += hv * wb2.y;
                hd_[6] += hv * wb2.z; hd_[7] += hv * wb2.w;
                hd_[8] += hv * wc2.x; hd_[9] += hv * wc2.y;
                hd_[10] += hv * wc2.z; hd_[11] += hv * wc2.w;
            }
#pragma unroll
            for (int j = 0; j < 12; j++) {
#pragma unroll
                for (int o = 16; o; o >>= 1)
                    hd_[j] += __shfl_xor_sync(0xffffffffu, hd_[j], o);
            }

            if (lane < 8) {
                outA[(size_t)row * AD + lane] = tanhf(hd_[lane] + bpv);
            } else if (lane == 8) {
                outV[row] = hd_[8] + bvv;
            } else if (lane == 9) {
                float z0 = hd_[9] + br0, z1 = hd_[10] + br1, z2 = hd_[11] + br2;
                float mx = fmaxf(z0, fmaxf(z1, z2));
                float e0 = expf(z0 - mx), e1 = expf(z1 - mx), e2 = expf(z2 - mx);
                float inv = 1.f / (e0 + e1 + e2);
                outR[(size_t)row * 3 + 0] = e0 * inv;
                outR[(size_t)row * 3 + 1] = e1 * inv;
                outR[(size_t)row * 3 + 2] = e2 * inv;
            }
        }
    }
}

#define FUSED_SMEM ((ROWS*SD + HD*CD + ROWS*HD + ROWS*33 + ROWS + CD + HD + HD + HD + 2*HD + HD*12) * 4)

extern "C" void kernel_launch(void* const* d_in, const int* in_sizes, int n_in,
                              void* d_out, int out_size) {
    const float* states = (const float*)d_in[0];
    const float* noise  = (const float*)d_in[1];
    const float* W1 = (const float*)d_in[2];
    const float* b1 = (const float*)d_in[3];
    const float* W2 = (const float*)d_in[4];
    const float* b2 = (const float*)d_in[5];
    const float* Wc = (const float*)d_in[6];
    const float* bc = (const float*)d_in[7];
    const float* Wg = (const float*)d_in[8];
    const float* bg = (const float*)d_in[9];
    const float* Wp = (const float*)d_in[10];
    const float* bp = (const float*)d_in[11];
    const float* Wv = (const float*)d_in[12];
    const float* bv = (const float*)d_in[13];
    const float* Wr = (const float*)d_in[14];
    const float* br = (const float*)d_in[15];

    float* outH = (float*)d_out;                       // [N, HD]
    float* outA = outH + (size_t)NA * HD;              // [N, AD]
    float* outV = outA + (size_t)NA * AD;              // [N, 1]
    float* outR = outV + (size_t)NA;                   // [N, 3]

    cudaFuncSetAttribute(kfused, cudaFuncAttributeMaxDynamicSharedMemorySize,
                         FUSED_SMEM);

    k0<<<CD, 128>>>(W2, Wc, b2, bc);
    kfused<<<NB, NT, FUSED_SMEM>>>(states, noise, W1, b1, W2, b2, Wg, bg,
                                   Wp, bp, Wv, bv, Wr, br,
                                   outH, outA, outV, outR);
}

// round 4
// speedup vs baseline: 1.2353x; 1.1471x over previous
#include <cuda_runtime.h>
#include <math.h>

#define NA 8192
#define SD 64
#define HD 128
#define CD 32
#define AD 8
#define NB 128      // fused grid (<= 148 SMs -> all resident, grid barrier safe)
#define NT 512
#define ROWS 64     // rows per block
#define RPT 16      // rows per thread in phases 1/3 (4 column-groups of 128)

// -------- device scratch --------
__device__ float g_W2c[HD * CD];    // W2 @ Wc
__device__ float g_bc2[CD];         // b2 @ Wc + bc
__device__ float g_msum[CD];        // sum of normalized msgs
__device__ float g_hsum[HD];        // column sum of relu(P + bias_eff)
__device__ unsigned g_barA, g_barB; // grid barrier counters (reset by k0)

// ============ K0: fold W2c, bc2; zero accumulators + barriers. 32 x 128 ======
__global__ void k0(const float* __restrict__ W2, const float* __restrict__ Wc,
                   const float* __restrict__ b2, const float* __restrict__ bc) {
    int c = blockIdx.x;   // 0..31
    int t = threadIdx.x;  // 0..127
    float acc = 0.f;
#pragma unroll 8
    for (int k = 0; k < HD; k++) acc += W2[t * HD + k] * Wc[k * CD + c];
    g_W2c[t * CD + c] = acc;
    if (t == 0) {
        float a = bc[c];
        for (int k = 0; k < HD; k++) a += b2[k] * Wc[k * CD + c];
        g_bc2[c] = a;
    }
    if (c == 0) {
        if (t < CD) g_msum[t] = 0.f;
        g_hsum[t] = 0.f;
        if (t == 0) { g_barA = 0u; g_barB = 0u; }
    }
}

// ---- software grid barrier (all NB blocks resident) ----
__device__ __forceinline__ void grid_barrier(unsigned* ctr) {
    __syncthreads();
    if (threadIdx.x == 0) {
        __threadfence();
        atomicAdd(ctr, 1u);
        while (*(volatile unsigned*)ctr < (unsigned)NB) {}
    }
    __syncthreads();
}

// ============ FUSED: k1 + k3 + k4 + k5 ============
__global__ void __launch_bounds__(NT, 1) kfused(
    const float* __restrict__ states, const float* __restrict__ noise,
    const float* __restrict__ W1, const float* __restrict__ b1,
    const float* __restrict__ W2, const float* __restrict__ b2,
    const float* __restrict__ Wg, const float* __restrict__ bg,
    const float* __restrict__ Wp, const float* __restrict__ bp,
    const float* __restrict__ Wv, const float* __restrict__ bv,
    const float* __restrict__ Wr, const float* __restrict__ br,
    float* __restrict__ outH, float* __restrict__ outA,
    float* __restrict__ outV, float* __restrict__ outR) {

    extern __shared__ float sm[];
    float* s_s   = sm;                    // ROWS*SD   = 4096
    float* s_w1  = s_s   + ROWS * SD;     // SD*HD     = 8192
    float* s_w2c = s_w1  + SD * HD;       // HD*CD     = 4096
    float* s_h   = s_w2c + HD * CD;       // ROWS*HD   = 8192
    float* s_msg = s_h   + ROWS * HD;     // ROWS*33   = 2112
    float* s_rn  = s_msg + ROWS * 33;     // 64
    float* s_bc2 = s_rn  + ROWS;          // 32
    float* s_mh  = s_bc2 + CD;            // 128
    float* s_h2  = s_mh  + HD;            // 128
    float* s_g   = s_h2  + HD;            // 128
    float* s_prt = s_g   + HD;            // 4*128 = 512
    float* s_col = s_prt + 4 * HD;        // 128
    float* s_hw  = s_col + HD;            // 1536

    int t = threadIdx.x;
    int r0 = blockIdx.x * ROWS;

    // ---- stage shared inputs ----
    for (int i = t; i < ROWS * SD; i += NT) s_s[i] = states[r0 * SD + i];
    for (int i = t; i < SD * HD; i += NT) s_w1[i] = W1[i];
    for (int i = t; i < HD * CD; i += NT) s_w2c[i] = g_W2c[i];
    if (t < CD) s_bc2[t] = g_bc2[t];
    for (int i = t; i < HD * 12; i += NT) {
        int k = i / 12, j = i % 12;
        float v;
        if (j < 8)       v = Wp[k * AD + j];
        else if (j == 8) v = Wv[k];
        else             v = Wr[k * 3 + (j - 9)];
        s_hw[i] = v;
    }
    __syncthreads();

    // ---- phase 1: P = states @ W1[:SD] (held in registers) ----
    int c = t & 127;              // output column
    int rb = (t >> 7) * RPT;      // row base (0,16,32,48)
    float bb = b1[c];
    float acc[RPT];
#pragma unroll
    for (int r = 0; r < RPT; r++) acc[r] = 0.f;

#pragma unroll 4
    for (int k = 0; k < SD; k += 4) {
        float w0 = s_w1[(k + 0) * HD + c];
        float w1v = s_w1[(k + 1) * HD + c];
        float w2v = s_w1[(k + 2) * HD + c];
        float w3v = s_w1[(k + 3) * HD + c];
#pragma unroll
        for (int r = 0; r < RPT; r++) {
            float4 sv = *(const float4*)&s_s[(rb + r) * SD + k];
            acc[r] += sv.x * w0 + sv.y * w1v + sv.z * w2v + sv.w * w3v;
        }
    }
#pragma unroll
    for (int r = 0; r < RPT; r++)
        s_h[(rb + r) * HD + c] = fmaxf(acc[r] + bb, 0.f);
    __syncthreads();

    // ---- phase 2: msgs = l2norm(relu(P+b1) @ W2c + bc2); accumulate msum ----
    {
        int mc = t & 31;          // msg column
        int rg = t >> 5;          // 0..15, 4 rows each
        float m[4];
#pragma unroll
        for (int r = 0; r < 4; r++) m[r] = s_bc2[mc];
#pragma unroll 4
        for (int k = 0; k < HD; k += 4) {
            float w0 = s_w2c[(k + 0) * CD + mc];
            float w1v = s_w2c[(k + 1) * CD + mc];
            float w2v = s_w2c[(k + 2) * CD + mc];
            float w3v = s_w2c[(k + 3) * CD + mc];
#pragma unroll
            for (int r = 0; r < 4; r++) {
                float4 hv = *(const float4*)&s_h[(rg * 4 + r) * HD + k];
                m[r] += hv.x * w0 + hv.y * w1v + hv.z * w2v + hv.w * w3v;
            }
        }
#pragma unroll
        for (int r = 0; r < 4; r++) s_msg[(rg * 4 + r) * 33 + mc] = m[r];
    }
    __syncthreads();
    if (t < ROWS) {
        float ss = 0.f;
#pragma unroll
        for (int j = 0; j < CD; j++) { float v = s_msg[t * 33 + j]; ss += v * v; }
        s_rn[t] = 1.f / fmaxf(sqrtf(ss), 1e-12f);
    }
    __syncthreads();
    if (t < CD) {
        float p = 0.f;
#pragma unroll
        for (int r = 0; r < ROWS; r++) p += s_msg[r * 33 + t] * s_rn[r];
        atomicAdd(&g_msum[t], p);
    }

    grid_barrier(&g_barA);

    // ---- phase 3: hsum[c] += sum_r relu(acc[r] + bias_eff[c]) ----
    if (t < CD) s_bc2[t] = *(volatile float*)&g_msum[t];  // reuse s_bc2
    if (t < HD) s_col[t] = 0.f;
    __syncthreads();
    {
        float be = bb;
#pragma unroll
        for (int j = 0; j < CD; j++)
            be += (s_bc2[j] * (1.0f / NA)) * W1[(SD + j) * HD + c];
        float hp = 0.f;
#pragma unroll
        for (int r = 0; r < RPT; r++) hp += fmaxf(acc[r] + be, 0.f);
        atomicAdd(&s_col[c], hp);
    }
    __syncthreads();
    if (t < HD) atomicAdd(&g_hsum[t], s_col[t]);

    grid_barrier(&g_barB);

    // ---- phase 4: g = relu((mean_h @ W2 + b2) @ Wg + bg), redundant/block ----
    if (t < HD) s_mh[t] = *(volatile float*)&g_hsum[t] * (1.0f / NA);
    __syncthreads();
    {
        int part = t >> 7;  // 0..3, 32 k each
        float w2r[32];
#pragma unroll
        for (int i = 0; i < 32; i++) w2r[i] = W2[(part * 32 + i) * HD + c];
        float a = 0.f;
#pragma unroll
        for (int i = 0; i < 32; i++) a += s_mh[part * 32 + i] * w2r[i];
        s_prt[part * HD + c] = a;
        __syncthreads();
        if (t < HD)
            s_h2[t] = b2[t] + s_prt[t] + s_prt[HD + t] + s_prt[2 * HD + t] +
                      s_prt[3 * HD + t];
        __syncthreads();
        float wgr[32];
#pragma unroll
        for (int i = 0; i < 32; i++) wgr[i] = Wg[(part * 32 + i) * HD + c];
        float g2 = 0.f;
#pragma unroll
        for (int i = 0; i < 32; i++) g2 += s_h2[part * 32 + i] * wgr[i];
        s_prt[part * HD + c] = g2;
        __syncthreads();
        if (t < HD)
            s_g[t] = fmaxf(bg[t] + s_prt[t] + s_prt[HD + t] + s_prt[2 * HD + t] +
                               s_prt[3 * HD + t], 0.f);
        __syncthreads();
    }

    // ---- phase 5: H = l2norm(g + 0.01*noise); heads. 4 rows per warp ----
    {
        int w = t >> 5, lane = t & 31;
        int rowb = r0 + w * 4;
        const float* nb = noise + (size_t)rowb * HD;
        float gp0 = s_g[lane +  0], gp1 = s_g[lane + 32];
        float gp2 = s_g[lane + 64], gp3 = s_g[lane + 96];
        float bpv = (lane < 8) ? bp[lane] : 0.f;
        float bvv = bv[0];
        float br0 = br[0], br1 = br[1], br2 = br[2];

        // front-batch all 16 noise loads (one DRAM round trip per warp)
        float nz[4][4];
#pragma unroll
        for (int i = 0; i < 4; i++) {
            nz[i][0] = nb[i * HD + lane +  0];
            nz[i][1] = nb[i * HD + lane + 32];
            nz[i][2] = nb[i * HD + lane + 64];
            nz[i][3] = nb[i * HD + lane + 96];
        }

#pragma unroll
        for (int i = 0; i < 4; i++) {
            int row = rowb + i;
            float v0 = gp0 + 0.01f * nz[i][0];
            float v1 = gp1 + 0.01f * nz[i][1];
            float v2 = gp2 + 0.01f * nz[i][2];
            float v3 = gp3 + 0.01f * nz[i][3];
            float ss = v0 * v0 + v1 * v1 + v2 * v2 + v3 * v3;
#pragma unroll
            for (int o = 16; o; o >>= 1) ss += __shfl_xor_sync(0xffffffffu, ss, o);
            float rn = 1.f / fmaxf(sqrtf(ss), 1e-12f);
            float h[4] = {v0 * rn, v1 * rn, v2 * rn, v3 * rn};

            float* oh = outH + (size_t)row * HD;
            oh[lane +  0] = h[0];
            oh[lane + 32] = h[1];
            oh[lane + 64] = h[2];
            oh[lane + 96] = h[3];

            float hd_[12];
#pragma unroll
            for (int j = 0; j < 12; j++) hd_[j] = 0.f;
#pragma unroll
            for (int m = 0; m < 4; m++) {
                int k = lane + 32 * m;
                const float4* wrow = (const float4*)&s_hw[k * 12];
                float4 wa = wrow[0], wb2 = wrow[1], wc2 = wrow[2];
                float hv = h[m];
                hd_[0] += hv * wa.x;  hd_[1] += hv * wa.y;
                hd_[2] += hv * wa.z;  hd_[3] += hv * wa.w;
                hd_[4] += hv * wb2.x; hd_[5] += hv * wb2.y;
                hd_[6] += hv * wb2.z; hd_[7] += hv * wb2.w;
                hd_[8] += hv * wc2.x; hd_[9] += hv * wc2.y;
                hd_[10] += hv * wc2.z; hd_[11] += hv * wc2.w;
            }
#pragma unroll
            for (int j = 0; j < 12; j++) {
#pragma unroll
                for (int o = 16; o; o >>= 1)
                    hd_[j] += __shfl_xor_sync(0xffffffffu, hd_[j], o);
            }

            if (lane < 8) {
                outA[(size_t)row * AD + lane] = tanhf(hd_[lane] + bpv);
            } else if (lane == 8) {
                outV[row] = hd_[8] + bvv;
            } else if (lane == 9) {
                float z0 = hd_[9] + br0, z1 = hd_[10] + br1, z2 = hd_[11] + br2;
                float mx = fmaxf(z0, fmaxf(z1, z2));
                float e0 = expf(z0 - mx), e1 = expf(z1 - mx), e2 = expf(z2 - mx);
                float inv = 1.f / (e0 + e1 + e2);
                outR[(size_t)row * 3 + 0] = e0 * inv;
                outR[(size_t)row * 3 + 1] = e1 * inv;
                outR[(size_t)row * 3 + 2] = e2 * inv;
            }
        }
    }
}

#define FUSED_SMEM ((ROWS*SD + SD*HD + HD*CD + ROWS*HD + ROWS*33 + ROWS + CD + \
                     HD + HD + HD + 4*HD + HD + HD*12) * 4)

extern "C" void kernel_launch(void* const* d_in, const int* in_sizes, int n_in,
                              void* d_out, int out_size) {
    const float* states = (const float*)d_in[0];
    const float* noise  = (const float*)d_in[1];
    const float* W1 = (const float*)d_in[2];
    const float* b1 = (const float*)d_in[3];
    const float* W2 = (const float*)d_in[4];
    const float* b2 = (const float*)d_in[5];
    const float* Wc = (const float*)d_in[6];
    const float* bc = (const float*)d_in[7];
    const float* Wg = (const float*)d_in[8];
    const float* bg = (const float*)d_in[9];
    const float* Wp = (const float*)d_in[10];
    const float* bp = (const float*)d_in[11];
    const float* Wv = (const float*)d_in[12];
    const float* bv = (const float*)d_in[13];
    const float* Wr = (const float*)d_in[14];
    const float* br = (const float*)d_in[15];

    float* outH = (float*)d_out;                       // [N, HD]
    float* outA = outH + (size_t)NA * HD;              // [N, AD]
    float* outV = outA + (size_t)NA * AD;              // [N, 1]
    float* outR = outV + (size_t)NA;                   // [N, 3]

    cudaFuncSetAttribute(kfused, cudaFuncAttributeMaxDynamicSharedMemorySize,
                         FUSED_SMEM);

    k0<<<CD, 128>>>(W2, Wc, b2, bc);
    kfused<<<NB, NT, FUSED_SMEM>>>(states, noise, W1, b1, W2, b2, Wg, bg,
                                   Wp, bp, Wv, bv, Wr, br,
                                   outH, outA, outV, outR);
}